// round 5
// baseline (speedup 1.0000x reference)
#include <cuda_runtime.h>
#include <cuda_bf16.h>
#include <cstdint>

// Problem constants (fixed shapes)
static constexpr int B_   = 64;
static constexpr int N_   = 2048;
static constexpr int D_   = 128;
static constexpr int K_   = 1024;          // ceil(0.5 * N)
static constexpr int BN_  = B_ * N_;       // 131072 nodes
static constexpr int BK_  = B_ * K_;       // 65536 kept nodes
static constexpr int DEG_ = 32;
static constexpr int EPG_ = N_ * DEG_;     // 65536 edges per graph
static constexpr int NPC_ = 8;             // CTAs per graph (deg & scatter)
static constexpr int EPC_ = EPG_ / NPC_;   // 8192 edges per CTA
static constexpr int NCTA_ = B_ * NPC_;    // 512

// fixed-point encoding: per-edge add  llround((m+16)*2^40) + (1<<56)
//   low 56 bits : sum of (m+16)*2^40  (always positive, < 2^51)
//   bits 56..63 : indeg count (< 256)
static constexpr unsigned long long TAG_  = 1ULL << 56;
static constexpr unsigned long long MASK_ = TAG_ - 1ULL;

// ---------------- scratch (device globals; no allocation allowed) ----------
__device__ int                g_odp[NCTA_ * N_];   // outdeg partials
__device__ unsigned long long g_spu[NCTA_ * N_];   // fused sum+indeg partials
__device__ unsigned long long g_mfx[BN_];          // encoded message per node
__device__ float  g_score[BN_];
__device__ float  g_t[BN_];
__device__ int    g_perm[BK_];
__device__ int    g_perm_com[BK_];
__device__ float  g_sumexp;

// monotonic float->uint mapping (for sort keys)
__device__ __forceinline__ unsigned int ford(float f) {
    unsigned int u = __float_as_uint(f);
    return (u & 0x80000000u) ? ~u : (u | 0x80000000u);
}

// error-free addition: s + e == a + b exactly.
__device__ __forceinline__ void two_sum(float a, float b, float& s, float& e) {
    float s_ = a + b;
    float bb = s_ - a;
    e = (a - (s_ - bb)) + (b - bb);
    s = s_;
}

// ---------------- kernels ---------------------------------------------------

// Per-CTA SMEM histogram of src -> outdeg partials. Also zero g_sumexp.
__global__ __launch_bounds__(256) void deg_kernel(const int* __restrict__ src) {
    __shared__ int h[N_];
    const int c = blockIdx.x;            // 0..511
    const int g = c >> 3, sub = c & 7;
    const int tid = threadIdx.x;
    for (int i = tid; i < N_; i += 256) h[i] = 0;
    if (c == 0 && tid == 0) g_sumexp = 0.0f;
    __syncthreads();

    const int4* p = reinterpret_cast<const int4*>(src + g * EPG_ + sub * EPC_);
    #pragma unroll
    for (int it = 0; it < EPC_ / (256 * 4); ++it) {
        int4 v = p[tid + it * 256];
        atomicAdd(&h[v.x & (N_ - 1)], 1);
        atomicAdd(&h[v.y & (N_ - 1)], 1);
        atomicAdd(&h[v.z & (N_ - 1)], 1);
        atomicAdd(&h[v.w & (N_ - 1)], 1);
    }
    __syncthreads();
    for (int i = tid; i < N_; i += 256) g_odp[c * N_ + i] = h[i];
}

// s = feature @ W (compensated fp32); merge outdeg partials in-warp;
// write encoded fixed-point message g_mfx. One warp per node row.
__global__ void proj_kernel(const float* __restrict__ feat, const float* __restrict__ W) {
    int gtid = blockIdx.x * blockDim.x + threadIdx.x;
    int w    = gtid >> 5;
    int lane = gtid & 31;
    if (w >= BN_) return;
    float4 f  = __ldg(reinterpret_cast<const float4*>(feat) + (size_t)w * 32 + lane);
    float4 wv = __ldg(reinterpret_cast<const float4*>(W) + lane);

    float p0 = f.x * wv.x, e0 = fmaf(f.x, wv.x, -p0);
    float p1 = f.y * wv.y, e1 = fmaf(f.y, wv.y, -p1);
    float p2 = f.z * wv.z, e2 = fmaf(f.z, wv.z, -p2);
    float p3 = f.w * wv.w, e3 = fmaf(f.w, wv.w, -p3);

    float hi, lo, err;
    two_sum(p0, p1, hi, lo);
    two_sum(hi, p2, hi, err); lo += err;
    two_sum(hi, p3, hi, err); lo += err;
    lo += (e0 + e1) + (e2 + e3);

    // outdeg partial: lanes 0..7 each read one plane
    int gph = w >> 11, l = w & (N_ - 1);
    int od = (lane < NPC_) ? g_odp[(gph * NPC_ + lane) * N_ + l] : 0;

    #pragma unroll
    for (int o = 16; o > 0; o >>= 1) {
        float h2 = __shfl_xor_sync(0xFFFFFFFFu, hi, o);
        float l2 = __shfl_xor_sync(0xFFFFFFFFu, lo, o);
        two_sum(hi, h2, hi, err);
        lo += l2 + err;
        od += __shfl_xor_sync(0xFFFFFFFFu, od, o);
    }
    if (lane == 0) {
        double s = (double)hi + (double)lo;
        double m = s / sqrt((double)max(od, 1));
        g_mfx[w] = (unsigned long long)llround((m + 16.0) * 0x1p40) + TAG_;
    }
}

// Fused scatter: one u64 SMEM atomic per edge accumulates score-sum + indeg.
// Messages staged in SMEM (gathers never leave the SM).
__global__ __launch_bounds__(256) void scatter_kernel(const int* __restrict__ src,
                                                      const int* __restrict__ dst) {
    __shared__ unsigned long long acc[N_];   // 16KB
    __shared__ unsigned long long msg[N_];   // 16KB
    const int c = blockIdx.x;
    const int g = c >> 3, sub = c & 7;
    const int tid = threadIdx.x;
    for (int i = tid; i < N_; i += 256) {
        acc[i] = 0ULL;
        msg[i] = g_mfx[g * N_ + i];
    }
    __syncthreads();

    const int4* ps = reinterpret_cast<const int4*>(src + g * EPG_ + sub * EPC_);
    const int4* pd = reinterpret_cast<const int4*>(dst + g * EPG_ + sub * EPC_);
    #pragma unroll
    for (int it = 0; it < EPC_ / (256 * 4); ++it) {
        int4 s4 = ps[tid + it * 256];
        int4 d4 = pd[tid + it * 256];
        atomicAdd(&acc[d4.x & (N_ - 1)], msg[s4.x & (N_ - 1)]);
        atomicAdd(&acc[d4.y & (N_ - 1)], msg[s4.y & (N_ - 1)]);
        atomicAdd(&acc[d4.z & (N_ - 1)], msg[s4.z & (N_ - 1)]);
        atomicAdd(&acc[d4.w & (N_ - 1)], msg[s4.w & (N_ - 1)]);
    }
    __syncthreads();
    for (int i = tid; i < N_; i += 256) g_spu[c * N_ + i] = acc[i];
}

// register-phase bitonic compare-exchange (j <= 16, within warp)
__device__ __forceinline__ void reg_ex(unsigned long long& key, int i, int j, int k) {
    unsigned long long p = __shfl_xor_sync(0xFFFFFFFFu, key, j);
    bool up  = ((i & k) == 0);
    bool low = ((i & j) == 0);
    unsigned long long mn = key < p ? key : p;
    unsigned long long mx = key < p ? p : key;
    key = (low == up) ? mn : mx;
}

// Fused finalize + per-graph sort.
//   score = decode(partials)/sqrt(indeg) + b; t=tanh; sumexp partial;
//   hybrid bitonic sort -> perm / perm_com.
__global__ __launch_bounds__(1024) void sortfin_kernel(const float* __restrict__ b,
                                                       float* __restrict__ out_perm,
                                                       float* __restrict__ out_perm_com) {
    __shared__ unsigned long long keys[N_];
    __shared__ int flags[N_];
    __shared__ float wsum[32];
    __shared__ int woff[33];

    const int g    = blockIdx.x;
    const int tid  = threadIdx.x;
    const int base = g * N_;
    const int i0 = tid, i1 = tid + 1024;
    const float bb = __ldg(b);

    // ---- finalize (2 nodes per thread, coalesced partial merge) ----
    float esum = 0.0f;
    unsigned long long k0, k1;
    #pragma unroll
    for (int r = 0; r < 2; r++) {
        int l = tid + r * 1024;
        unsigned long long a = 0ULL;
        #pragma unroll
        for (int p = 0; p < NPC_; ++p) a += g_spu[(g * NPC_ + p) * N_ + l];
        int id = (int)(a >> 56);
        double sum = (double)(a & MASK_) * 0x1p-40 - 16.0 * (double)id;
        double sd = sum / sqrt((double)max(id, 1)) + (double)bb;
        float sc = (float)sd;
        g_score[base + l] = sc;
        g_t[base + l] = tanhf(sc);
        esum += __expf(sc);
        unsigned long long kk =
            ((unsigned long long)(~ford(sc)) << 32) | (unsigned int)l;
        if (r == 0) k0 = kk; else k1 = kk;
    }
    // block-reduce esum -> g_sumexp
    #pragma unroll
    for (int o = 16; o > 0; o >>= 1) esum += __shfl_xor_sync(0xFFFFFFFFu, esum, o);
    if ((tid & 31) == 0) wsum[tid >> 5] = esum;
    __syncthreads();
    if (tid < 32) {
        float e = wsum[tid];
        #pragma unroll
        for (int o = 16; o > 0; o >>= 1) e += __shfl_xor_sync(0xFFFFFFFFu, e, o);
        if (tid == 0) atomicAdd(&g_sumexp, e);
    }

    // ---- bitonic sort: k=2..32 in registers ----
    #pragma unroll
    for (int k = 2; k <= 32; k <<= 1)
        for (int j = k >> 1; j >= 1; j >>= 1) { reg_ex(k0, i0, j, k); reg_ex(k1, i1, j, k); }

    // k = 64..2048: SMEM passes for j>=32, register passes for j<=16
    for (int k = 64; k <= N_; k <<= 1) {
        keys[i0] = k0; keys[i1] = k1;
        __syncthreads();
        for (int j = k >> 1; j >= 32; j >>= 1) {
            #pragma unroll
            for (int r = 0; r < 2; r++) {
                int i = tid + r * 1024;
                int ixj = i ^ j;
                if (ixj > i) {
                    unsigned long long a = keys[i], c = keys[ixj];
                    bool up = ((i & k) == 0);
                    if ((a > c) == up) { keys[i] = c; keys[ixj] = a; }
                }
            }
            __syncthreads();
        }
        k0 = keys[i0]; k1 = keys[i1];
        #pragma unroll
        for (int j = 16; j >= 1; j >>= 1) { reg_ex(k0, i0, j, k); reg_ex(k1, i1, j, k); }
    }
    keys[i0] = k0; keys[i1] = k1;
    __syncthreads();

    // flags: 1 = unselected
    flags[i0] = 1; flags[i1] = 1;
    __syncthreads();

    // top K_ = first 1024 sorted entries
    {
        int local = (int)(unsigned int)(keys[tid] & 0xFFFFFFFFull);
        flags[local] = 0;
        int gid = base + local;
        g_perm[g * K_ + tid]   = gid;
        out_perm[g * K_ + tid] = (float)gid;
    }
    __syncthreads();

    // warp-shfl scan over contiguous pairs (3 syncs total)
    {
        int e0 = 2 * tid, e1 = 2 * tid + 1;
        int f0 = flags[e0], f1 = flags[e1];
        int v = f0 + f1;
        int sv = v;
        #pragma unroll
        for (int o = 1; o < 32; o <<= 1) {
            int n = __shfl_up_sync(0xFFFFFFFFu, sv, o);
            if ((tid & 31) >= o) sv += n;
        }
        if ((tid & 31) == 31) woff[(tid >> 5) + 1] = sv;
        __syncthreads();
        if (tid == 0) {
            int run = 0;
            woff[0] = 0;
            #pragma unroll
            for (int wgi = 1; wgi <= 32; ++wgi) { run += woff[wgi]; woff[wgi] = run; }
        }
        __syncthreads();
        int pre = woff[tid >> 5] + (sv - v);     // exclusive prefix for e0
        if (f0) {
            int pos = pre;
            g_perm_com[g * (N_ - K_) + pos]   = base + e0;
            out_perm_com[g * (N_ - K_) + pos] = (float)(base + e0);
        }
        if (f1) {
            int pos = pre + f0;
            g_perm_com[g * (N_ - K_) + pos]   = base + e1;
            out_perm_com[g * (N_ - K_) + pos] = (float)(base + e1);
        }
    }
}

// Emit feature_full (+score_sm), feature_dist, feature_com. One warp per row.
__global__ void emit_kernel(const float* __restrict__ feat,
                            float* __restrict__ out_dist,
                            float* __restrict__ out_com,
                            float* __restrict__ out_full,
                            float* __restrict__ out_sm) {
    int gtid = blockIdx.x * blockDim.x + threadIdx.x;
    int w    = gtid >> 5;
    int lane = gtid & 31;
    const int TW = BN_ + BK_ + BK_;
    if (w >= TW) return;

    int p;           // source node
    float* outp;     // destination row
    if (w < BN_) {
        p = w;
        outp = out_full + (size_t)w * D_;
        if (lane == 0) {
            __stcs(out_sm + w, __expf(g_score[w]) / g_sumexp);
        }
    } else if (w < BN_ + BK_) {
        int r = w - BN_;
        p = g_perm[r];
        outp = out_dist + (size_t)r * D_;
    } else {
        int r = w - BN_ - BK_;
        p = g_perm_com[r];
        outp = out_com + (size_t)r * D_;
    }

    float t = g_t[p];
    float4 f = __ldg(reinterpret_cast<const float4*>(feat) + (size_t)p * 32 + lane);
    f.x *= t; f.y *= t; f.z *= t; f.w *= t;
    __stcs(reinterpret_cast<float4*>(outp) + lane, f);
}

// ---------------- launch ----------------------------------------------------

extern "C" void kernel_launch(void* const* d_in, const int* in_sizes, int n_in,
                              void* d_out, int out_size) {
    const float* feature = (const float*)d_in[0];
    const float* W       = (const float*)d_in[1];
    const float* b       = (const float*)d_in[2];
    const int*   src     = (const int*)d_in[3];
    const int*   dst     = (const int*)d_in[4];

    float* out = (float*)d_out;
    float* out_dist     = out;                                  // BK_*D_
    float* out_com      = out + (size_t)BK_ * D_;               // BK_*D_
    float* out_full     = out + (size_t)2 * BK_ * D_;           // BN_*D_
    float* out_perm     = out + (size_t)2 * BK_ * D_ + (size_t)BN_ * D_;
    float* out_perm_com = out_perm + BK_;
    float* out_sm       = out_perm_com + BK_;

    deg_kernel<<<NCTA_, 256>>>(src);
    proj_kernel<<<(BN_ * 32 + 255) / 256, 256>>>(feature, W);
    scatter_kernel<<<NCTA_, 256>>>(src, dst);
    sortfin_kernel<<<B_, 1024>>>(b, out_perm, out_perm_com);
    {
        const int TW = BN_ + BK_ + BK_;
        emit_kernel<<<((size_t)TW * 32 + 255) / 256, 256>>>(
            feature, out_dist, out_com, out_full, out_sm);
    }
}

// round 6
// speedup vs baseline: 1.0563x; 1.0563x over previous
#include <cuda_runtime.h>
#include <cuda_bf16.h>
#include <cstdint>

// Problem constants (fixed shapes)
static constexpr int B_   = 64;
static constexpr int N_   = 2048;
static constexpr int D_   = 128;
static constexpr int K_   = 1024;          // ceil(0.5 * N)
static constexpr int BN_  = B_ * N_;       // 131072 nodes
static constexpr int BK_  = B_ * K_;       // 65536 kept nodes
static constexpr int DEG_ = 32;
static constexpr int EPG_ = N_ * DEG_;     // 65536 edges per graph
static constexpr int NPC_ = 8;             // CTAs per graph (deg & scatter)
static constexpr int EPC_ = EPG_ / NPC_;   // 8192 edges per CTA
static constexpr int NCTA_ = B_ * NPC_;    // 512

// fixed-point encoding: per-edge add  llround((m+16)*2^40) + (1<<56)
//   low 56 bits : sum of (m+16)*2^40  (positive, < 2^51 per partial)
//   bits 56..63 : indeg count (< 256 after merge)
static constexpr unsigned long long TAG_  = 1ULL << 56;
static constexpr unsigned long long MASK_ = TAG_ - 1ULL;
static constexpr int COM_BIT = 1 << 30;

// ---------------- scratch (device globals; no allocation allowed) ----------
__device__ int                g_odp[NCTA_ * N_];   // outdeg partials
__device__ unsigned long long g_spu[NCTA_ * N_];   // fused sum+indeg partials
__device__ unsigned long long g_mfx[BN_];          // encoded message per node
__device__ float  g_score[BN_];
__device__ float  g_t[BN_];
__device__ int    g_inv[BN_];                      // node -> dist/com row
__device__ float  g_sumexp;

// monotonic float->uint mapping (for sort keys)
__device__ __forceinline__ unsigned int ford(float f) {
    unsigned int u = __float_as_uint(f);
    return (u & 0x80000000u) ? ~u : (u | 0x80000000u);
}

// error-free addition: s + e == a + b exactly.
__device__ __forceinline__ void two_sum(float a, float b, float& s, float& e) {
    float s_ = a + b;
    float bb = s_ - a;
    e = (a - (s_ - bb)) + (b - bb);
    s = s_;
}

// ---------------- kernels ---------------------------------------------------

// Per-CTA SMEM histogram of src -> outdeg partials. Also zero g_sumexp.
__global__ __launch_bounds__(256) void deg_kernel(const int* __restrict__ src) {
    __shared__ int h[N_];
    const int c = blockIdx.x;            // 0..511
    const int g = c >> 3, sub = c & 7;
    const int tid = threadIdx.x;
    for (int i = tid; i < N_; i += 256) h[i] = 0;
    if (c == 0 && tid == 0) g_sumexp = 0.0f;
    __syncthreads();

    const int4* p = reinterpret_cast<const int4*>(src + g * EPG_ + sub * EPC_);
    #pragma unroll
    for (int it = 0; it < EPC_ / (256 * 4); ++it) {
        int4 v = p[tid + it * 256];
        atomicAdd(&h[v.x & (N_ - 1)], 1);
        atomicAdd(&h[v.y & (N_ - 1)], 1);
        atomicAdd(&h[v.z & (N_ - 1)], 1);
        atomicAdd(&h[v.w & (N_ - 1)], 1);
    }
    __syncthreads();
    for (int i = tid; i < N_; i += 256) g_odp[c * N_ + i] = h[i];
}

// s = feature @ W (compensated fp32); merge outdeg partials in-warp;
// write encoded fixed-point message g_mfx. One warp per node row.
__global__ void proj_kernel(const float* __restrict__ feat, const float* __restrict__ W) {
    int gtid = blockIdx.x * blockDim.x + threadIdx.x;
    int w    = gtid >> 5;
    int lane = gtid & 31;
    if (w >= BN_) return;
    float4 f  = __ldg(reinterpret_cast<const float4*>(feat) + (size_t)w * 32 + lane);
    float4 wv = __ldg(reinterpret_cast<const float4*>(W) + lane);

    float p0 = f.x * wv.x, e0 = fmaf(f.x, wv.x, -p0);
    float p1 = f.y * wv.y, e1 = fmaf(f.y, wv.y, -p1);
    float p2 = f.z * wv.z, e2 = fmaf(f.z, wv.z, -p2);
    float p3 = f.w * wv.w, e3 = fmaf(f.w, wv.w, -p3);

    float hi, lo, err;
    two_sum(p0, p1, hi, lo);
    two_sum(hi, p2, hi, err); lo += err;
    two_sum(hi, p3, hi, err); lo += err;
    lo += (e0 + e1) + (e2 + e3);

    // outdeg partial: lanes 0..7 each read one plane
    int gph = w >> 11, l = w & (N_ - 1);
    int od = (lane < NPC_) ? g_odp[(gph * NPC_ + lane) * N_ + l] : 0;

    #pragma unroll
    for (int o = 16; o > 0; o >>= 1) {
        float h2 = __shfl_xor_sync(0xFFFFFFFFu, hi, o);
        float l2 = __shfl_xor_sync(0xFFFFFFFFu, lo, o);
        two_sum(hi, h2, hi, err);
        lo += l2 + err;
        od += __shfl_xor_sync(0xFFFFFFFFu, od, o);
    }
    if (lane == 0) {
        double s = (double)hi + (double)lo;
        double m = s / sqrt((double)max(od, 1));
        g_mfx[w] = (unsigned long long)llround((m + 16.0) * 0x1p40) + TAG_;
    }
}

// Fused scatter: one u64 SMEM atomic per edge accumulates score-sum + indeg.
// Messages staged in SMEM (gathers never leave the SM).
__global__ __launch_bounds__(256) void scatter_kernel(const int* __restrict__ src,
                                                      const int* __restrict__ dst) {
    __shared__ unsigned long long acc[N_];   // 16KB
    __shared__ unsigned long long msg[N_];   // 16KB
    const int c = blockIdx.x;
    const int g = c >> 3, sub = c & 7;
    const int tid = threadIdx.x;
    for (int i = tid; i < N_; i += 256) {
        acc[i] = 0ULL;
        msg[i] = g_mfx[g * N_ + i];
    }
    __syncthreads();

    const int4* ps = reinterpret_cast<const int4*>(src + g * EPG_ + sub * EPC_);
    const int4* pd = reinterpret_cast<const int4*>(dst + g * EPG_ + sub * EPC_);
    #pragma unroll
    for (int it = 0; it < EPC_ / (256 * 4); ++it) {
        int4 s4 = ps[tid + it * 256];
        int4 d4 = pd[tid + it * 256];
        atomicAdd(&acc[d4.x & (N_ - 1)], msg[s4.x & (N_ - 1)]);
        atomicAdd(&acc[d4.y & (N_ - 1)], msg[s4.y & (N_ - 1)]);
        atomicAdd(&acc[d4.z & (N_ - 1)], msg[s4.z & (N_ - 1)]);
        atomicAdd(&acc[d4.w & (N_ - 1)], msg[s4.w & (N_ - 1)]);
    }
    __syncthreads();
    for (int i = tid; i < N_; i += 256) g_spu[c * N_ + i] = acc[i];
}

// Merge 8 u64 partials (fixed order -> deterministic); decode;
// score = sum/sqrt(indeg) + b ; t = tanh ; block-reduced sumexp.
__global__ void finalize_kernel(const float* __restrict__ b) {
    int v = blockIdx.x * blockDim.x + threadIdx.x;
    float e = 0.0f;
    if (v < BN_) {
        int g = v >> 11, l = v & (N_ - 1);
        unsigned long long a = 0ULL;
        #pragma unroll
        for (int p = 0; p < NPC_; ++p) a += g_spu[(g * NPC_ + p) * N_ + l];
        int id = (int)(a >> 56);
        double sum = (double)(a & MASK_) * 0x1p-40 - 16.0 * (double)id;
        double sd = sum / sqrt((double)max(id, 1)) + (double)__ldg(b);
        float sc = (float)sd;
        g_score[v] = sc;
        g_t[v] = tanhf(sc);
        e = __expf(sc);
    }
    __shared__ float sm[32];
    #pragma unroll
    for (int o = 16; o > 0; o >>= 1) e += __shfl_xor_sync(0xFFFFFFFFu, e, o);
    int lane = threadIdx.x & 31, wid = threadIdx.x >> 5;
    if (lane == 0) sm[wid] = e;
    __syncthreads();
    if (wid == 0) {
        e = (lane < (blockDim.x >> 5)) ? sm[lane] : 0.0f;
        #pragma unroll
        for (int o = 16; o > 0; o >>= 1) e += __shfl_xor_sync(0xFFFFFFFFu, e, o);
        if (lane == 0) atomicAdd(&g_sumexp, e);
    }
}

// register-phase bitonic compare-exchange (j <= 16, within warp)
__device__ __forceinline__ void reg_ex(unsigned long long& key, int i, int j, int k) {
    unsigned long long p = __shfl_xor_sync(0xFFFFFFFFu, key, j);
    bool up  = ((i & k) == 0);
    bool low = ((i & j) == 0);
    unsigned long long mn = key < p ? key : p;
    unsigned long long mx = key < p ? p : key;
    key = (low == up) ? mn : mx;
}

// Per-graph hybrid bitonic sort -> out_perm / out_perm_com + inverse map g_inv.
__global__ __launch_bounds__(1024) void sort_kernel(float* __restrict__ out_perm,
                                                    float* __restrict__ out_perm_com) {
    __shared__ unsigned long long keys[N_];
    __shared__ int flags[N_];
    __shared__ int woff[33];

    const int g    = blockIdx.x;
    const int tid  = threadIdx.x;
    const int base = g * N_;
    const int i0 = tid, i1 = tid + 1024;

    unsigned long long k0, k1;
    {
        unsigned int a = ~ford(g_score[base + i0]);
        unsigned int b = ~ford(g_score[base + i1]);
        k0 = ((unsigned long long)a << 32) | (unsigned int)i0;
        k1 = ((unsigned long long)b << 32) | (unsigned int)i1;
    }

    // k = 2..32 entirely in registers
    #pragma unroll
    for (int k = 2; k <= 32; k <<= 1)
        for (int j = k >> 1; j >= 1; j >>= 1) { reg_ex(k0, i0, j, k); reg_ex(k1, i1, j, k); }

    // k = 64..2048: SMEM passes for j>=32, register passes for j<=16
    for (int k = 64; k <= N_; k <<= 1) {
        keys[i0] = k0; keys[i1] = k1;
        __syncthreads();
        for (int j = k >> 1; j >= 32; j >>= 1) {
            #pragma unroll
            for (int r = 0; r < 2; r++) {
                int i = tid + r * 1024;
                int ixj = i ^ j;
                if (ixj > i) {
                    unsigned long long a = keys[i], c = keys[ixj];
                    bool up = ((i & k) == 0);
                    if ((a > c) == up) { keys[i] = c; keys[ixj] = a; }
                }
            }
            __syncthreads();
        }
        k0 = keys[i0]; k1 = keys[i1];
        #pragma unroll
        for (int j = 16; j >= 1; j >>= 1) { reg_ex(k0, i0, j, k); reg_ex(k1, i1, j, k); }
    }
    keys[i0] = k0; keys[i1] = k1;
    __syncthreads();

    // flags: 1 = unselected
    flags[i0] = 1; flags[i1] = 1;
    __syncthreads();

    // top K_ = first 1024 sorted entries: perm + inverse map
    {
        int local = (int)(unsigned int)(keys[tid] & 0xFFFFFFFFull);
        flags[local] = 0;
        g_inv[base + local]    = g * K_ + tid;           // dist row
        out_perm[g * K_ + tid] = (float)(base + local);
    }
    __syncthreads();

    // warp-shfl scan over contiguous pairs (3 syncs total)
    {
        int e0 = 2 * tid, e1 = 2 * tid + 1;
        int f0 = flags[e0], f1 = flags[e1];
        int v = f0 + f1;
        int sv = v;
        #pragma unroll
        for (int o = 1; o < 32; o <<= 1) {
            int n = __shfl_up_sync(0xFFFFFFFFu, sv, o);
            if ((tid & 31) >= o) sv += n;
        }
        if ((tid & 31) == 31) woff[(tid >> 5) + 1] = sv;
        __syncthreads();
        if (tid == 0) {
            int run = 0;
            woff[0] = 0;
            #pragma unroll
            for (int wgi = 1; wgi <= 32; ++wgi) { run += woff[wgi]; woff[wgi] = run; }
        }
        __syncthreads();
        int pre = woff[tid >> 5] + (sv - v);     // exclusive prefix for e0
        if (f0) {
            int pos = g * (N_ - K_) + pre;
            g_inv[base + e0] = pos | COM_BIT;
            out_perm_com[pos] = (float)(base + e0);
        }
        if (f1) {
            int pos = g * (N_ - K_) + pre + f0;
            g_inv[base + e1] = pos | COM_BIT;
            out_perm_com[pos] = (float)(base + e1);
        }
    }
}

// Emit: one warp per NODE. Read feature row once, scale by t, write to
// feature_full AND its dist/com slot (inverse permutation). Also score_sm.
__global__ void emit_kernel(const float* __restrict__ feat,
                            float* __restrict__ out_dist,
                            float* __restrict__ out_com,
                            float* __restrict__ out_full,
                            float* __restrict__ out_sm) {
    int gtid = blockIdx.x * blockDim.x + threadIdx.x;
    int w    = gtid >> 5;
    int lane = gtid & 31;
    if (w >= BN_) return;

    float t = g_t[w];
    float4 f = __ldg(reinterpret_cast<const float4*>(feat) + (size_t)w * 32 + lane);
    f.x *= t; f.y *= t; f.z *= t; f.w *= t;

    reinterpret_cast<float4*>(out_full + (size_t)w * D_)[lane] = f;

    int r = g_inv[w];
    float* o2 = (r & COM_BIT) ? out_com + (size_t)(r & (COM_BIT - 1)) * D_
                              : out_dist + (size_t)r * D_;
    reinterpret_cast<float4*>(o2)[lane] = f;

    if (lane == 0) {
        out_sm[w] = __expf(g_score[w]) / g_sumexp;
    }
}

// ---------------- launch ----------------------------------------------------

extern "C" void kernel_launch(void* const* d_in, const int* in_sizes, int n_in,
                              void* d_out, int out_size) {
    const float* feature = (const float*)d_in[0];
    const float* W       = (const float*)d_in[1];
    const float* b       = (const float*)d_in[2];
    const int*   src     = (const int*)d_in[3];
    const int*   dst     = (const int*)d_in[4];

    float* out = (float*)d_out;
    float* out_dist     = out;                                  // BK_*D_
    float* out_com      = out + (size_t)BK_ * D_;               // BK_*D_
    float* out_full     = out + (size_t)2 * BK_ * D_;           // BN_*D_
    float* out_perm     = out + (size_t)2 * BK_ * D_ + (size_t)BN_ * D_;
    float* out_perm_com = out_perm + BK_;
    float* out_sm       = out_perm_com + BK_;

    deg_kernel<<<NCTA_, 256>>>(src);
    proj_kernel<<<(BN_ * 32 + 255) / 256, 256>>>(feature, W);
    scatter_kernel<<<NCTA_, 256>>>(src, dst);
    finalize_kernel<<<(BN_ + 255) / 256, 256>>>(b);
    sort_kernel<<<B_, 1024>>>(out_perm, out_perm_com);
    emit_kernel<<<((size_t)BN_ * 32 + 255) / 256, 256>>>(
        feature, out_dist, out_com, out_full, out_sm);
}

// round 7
// speedup vs baseline: 2.3195x; 2.1958x over previous
#include <cuda_runtime.h>
#include <cuda_bf16.h>
#include <cstdint>

// Problem constants (fixed shapes)
static constexpr int B_   = 64;
static constexpr int N_   = 2048;
static constexpr int D_   = 128;
static constexpr int K_   = 1024;          // ceil(0.5 * N)
static constexpr int BN_  = B_ * N_;       // 131072 nodes
static constexpr int BK_  = B_ * K_;       // 65536 kept nodes
static constexpr int EPG_ = N_ * 32;       // 65536 edges per graph
static constexpr int NPC_ = 8;             // CTAs per graph (deg & scatter)
static constexpr int EPC_ = EPG_ / NPC_;   // 8192 edges per CTA
static constexpr int NCTA_ = B_ * NPC_;    // 512

// fixed-point encoding: per-edge add  llround((m+16)*2^40) + (1<<56)
//   low 56 bits : sum of (m+16)*2^40  (positive)
//   bits 56..63 : indeg count (< 256 after merge)
static constexpr unsigned long long TAG_  = 1ULL << 56;
static constexpr unsigned long long MASK_ = TAG_ - 1ULL;

// ---------------- scratch (device globals; no allocation allowed) ----------
__device__ int                g_odp[NCTA_ * N_];   // outdeg partials
__device__ unsigned long long g_spu[NCTA_ * N_];   // fused sum+indeg partials
__device__ float2             g_s[BN_];            // dot product (hi, lo)
__device__ unsigned long long g_mfx[BN_];          // encoded message per node
__device__ float  g_score[BN_];
__device__ float  g_t[BN_];
__device__ int    g_perm[BK_];                     // kept rows   (global ids)
__device__ int    g_permc[BK_];                    // dropped rows (global ids)
__device__ float  g_sumexp;

// monotonic float->uint mapping (for sort keys)
__device__ __forceinline__ unsigned int ford(float f) {
    unsigned int u = __float_as_uint(f);
    return (u & 0x80000000u) ? ~u : (u | 0x80000000u);
}

// error-free addition: s + e == a + b exactly.
__device__ __forceinline__ void two_sum(float a, float b, float& s, float& e) {
    float s_ = a + b;
    float bb = s_ - a;
    e = (a - (s_ - bb)) + (b - bb);
    s = s_;
}

// ---------------- kernels ---------------------------------------------------

// Grid-fused: blocks [0,512) = src histogram (SMEM-atomic bound);
//             blocks [512,1024) = compensated dot (DRAM bound).
__global__ __launch_bounds__(256) void degdot_kernel(const int* __restrict__ src,
                                                     const float* __restrict__ feat,
                                                     const float* __restrict__ W) {
    const int tid = threadIdx.x;
    if (blockIdx.x < NCTA_) {
        // ---- deg path ----
        __shared__ int h[N_];
        const int c = blockIdx.x;
        const int g = c >> 3, sub = c & 7;
        for (int i = tid; i < N_; i += 256) h[i] = 0;
        if (c == 0 && tid == 0) g_sumexp = 0.0f;
        __syncthreads();
        const int4* p = reinterpret_cast<const int4*>(src + g * EPG_ + sub * EPC_);
        #pragma unroll
        for (int it = 0; it < EPC_ / (256 * 4); ++it) {
            int4 v = p[tid + it * 256];
            atomicAdd(&h[v.x & (N_ - 1)], 1);
            atomicAdd(&h[v.y & (N_ - 1)], 1);
            atomicAdd(&h[v.z & (N_ - 1)], 1);
            atomicAdd(&h[v.w & (N_ - 1)], 1);
        }
        __syncthreads();
        for (int i = tid; i < N_; i += 256) g_odp[c * N_ + i] = h[i];
    } else {
        // ---- dot path: 8 warps x 32 rows each ----
        const int c2   = blockIdx.x - NCTA_;          // 0..511
        const int wip  = tid >> 5;                    // warp in block
        const int lane = tid & 31;
        const int row0 = c2 * 256 + wip * 32;
        const float4 wv = __ldg(reinterpret_cast<const float4*>(W) + lane);
        for (int i = 0; i < 32; ++i) {
            int w = row0 + i;
            float4 f = __ldg(reinterpret_cast<const float4*>(feat) + (size_t)w * 32 + lane);
            float p0 = f.x * wv.x, e0 = fmaf(f.x, wv.x, -p0);
            float p1 = f.y * wv.y, e1 = fmaf(f.y, wv.y, -p1);
            float p2 = f.z * wv.z, e2 = fmaf(f.z, wv.z, -p2);
            float p3 = f.w * wv.w, e3 = fmaf(f.w, wv.w, -p3);
            float hi, lo, err;
            two_sum(p0, p1, hi, lo);
            two_sum(hi, p2, hi, err); lo += err;
            two_sum(hi, p3, hi, err); lo += err;
            lo += (e0 + e1) + (e2 + e3);
            #pragma unroll
            for (int o = 16; o > 0; o >>= 1) {
                float h2 = __shfl_xor_sync(0xFFFFFFFFu, hi, o);
                float l2 = __shfl_xor_sync(0xFFFFFFFFu, lo, o);
                two_sum(hi, h2, hi, err);
                lo += l2 + err;
            }
            if (lane == 0) g_s[w] = make_float2(hi, lo);
        }
    }
}

// Merge outdeg partials + encode fixed-point message. One thread per node.
__global__ void msg_kernel() {
    int v = blockIdx.x * blockDim.x + threadIdx.x;
    if (v >= BN_) return;
    int g = v >> 11, l = v & (N_ - 1);
    int od = 0;
    #pragma unroll
    for (int p = 0; p < NPC_; ++p) od += g_odp[(g * NPC_ + p) * N_ + l];
    float2 s2 = g_s[v];
    double s = (double)s2.x + (double)s2.y;
    double m = s / sqrt((double)max(od, 1));
    g_mfx[v] = (unsigned long long)llround((m + 16.0) * 0x1p40) + TAG_;
}

// Fused scatter: one u64 SMEM atomic per edge accumulates score-sum + indeg.
__global__ __launch_bounds__(256) void scatter_kernel(const int* __restrict__ src,
                                                      const int* __restrict__ dst) {
    __shared__ unsigned long long acc[N_];   // 16KB
    __shared__ unsigned long long msg[N_];   // 16KB
    const int c = blockIdx.x;
    const int g = c >> 3, sub = c & 7;
    const int tid = threadIdx.x;
    for (int i = tid; i < N_; i += 256) {
        acc[i] = 0ULL;
        msg[i] = g_mfx[g * N_ + i];
    }
    __syncthreads();

    const int4* ps = reinterpret_cast<const int4*>(src + g * EPG_ + sub * EPC_);
    const int4* pd = reinterpret_cast<const int4*>(dst + g * EPG_ + sub * EPC_);
    #pragma unroll
    for (int it = 0; it < EPC_ / (256 * 4); ++it) {
        int4 s4 = ps[tid + it * 256];
        int4 d4 = pd[tid + it * 256];
        atomicAdd(&acc[d4.x & (N_ - 1)], msg[s4.x & (N_ - 1)]);
        atomicAdd(&acc[d4.y & (N_ - 1)], msg[s4.y & (N_ - 1)]);
        atomicAdd(&acc[d4.z & (N_ - 1)], msg[s4.z & (N_ - 1)]);
        atomicAdd(&acc[d4.w & (N_ - 1)], msg[s4.w & (N_ - 1)]);
    }
    __syncthreads();
    for (int i = tid; i < N_; i += 256) g_spu[c * N_ + i] = acc[i];
}

// Merge 8 u64 partials (fixed order -> deterministic); decode;
// score = sum/sqrt(indeg) + b ; t = tanh ; block-reduced sumexp.
__global__ void finalize_kernel(const float* __restrict__ b) {
    int v = blockIdx.x * blockDim.x + threadIdx.x;
    float e = 0.0f;
    if (v < BN_) {
        int g = v >> 11, l = v & (N_ - 1);
        unsigned long long a = 0ULL;
        #pragma unroll
        for (int p = 0; p < NPC_; ++p) a += g_spu[(g * NPC_ + p) * N_ + l];
        int id = (int)(a >> 56);
        double sum = (double)(a & MASK_) * 0x1p-40 - 16.0 * (double)id;
        double sd = sum / sqrt((double)max(id, 1)) + (double)__ldg(b);
        float sc = (float)sd;
        g_score[v] = sc;
        g_t[v] = tanhf(sc);
        e = __expf(sc);
    }
    __shared__ float sm[32];
    #pragma unroll
    for (int o = 16; o > 0; o >>= 1) e += __shfl_xor_sync(0xFFFFFFFFu, e, o);
    int lane = threadIdx.x & 31, wid = threadIdx.x >> 5;
    if (lane == 0) sm[wid] = e;
    __syncthreads();
    if (wid == 0) {
        e = (lane < (blockDim.x >> 5)) ? sm[lane] : 0.0f;
        #pragma unroll
        for (int o = 16; o > 0; o >>= 1) e += __shfl_xor_sync(0xFFFFFFFFu, e, o);
        if (lane == 0) atomicAdd(&g_sumexp, e);
    }
}

// register-phase bitonic compare-exchange (j <= 16, within warp)
__device__ __forceinline__ void reg_ex(unsigned long long& key, int i, int j, int k) {
    unsigned long long p = __shfl_xor_sync(0xFFFFFFFFu, key, j);
    bool up  = ((i & k) == 0);
    bool low = ((i & j) == 0);
    unsigned long long mn = key < p ? key : p;
    unsigned long long mx = key < p ? p : key;
    key = (low == up) ? mn : mx;
}

// Grid-fused: blocks [0,64) = per-graph sort -> perms;
//             blocks [64, 64+4096) = emit feature_full + score_sm.
// Both depend only on finalize outputs.
__global__ __launch_bounds__(1024) void sortemit_kernel(const float* __restrict__ feat,
                                                        float* __restrict__ out_perm,
                                                        float* __restrict__ out_perm_com,
                                                        float* __restrict__ out_full,
                                                        float* __restrict__ out_sm) {
    __shared__ unsigned long long keys[N_];
    __shared__ int flags[N_];
    __shared__ int woff[33];

    const int tid = threadIdx.x;

    if (blockIdx.x >= B_) {
        // ---- emit_full path: one warp per node row ----
        int w    = (blockIdx.x - B_) * 32 + (tid >> 5);
        int lane = tid & 31;
        float t = g_t[w];
        float4 f = __ldg(reinterpret_cast<const float4*>(feat) + (size_t)w * 32 + lane);
        f.x *= t; f.y *= t; f.z *= t; f.w *= t;
        reinterpret_cast<float4*>(out_full + (size_t)w * D_)[lane] = f;
        if (lane == 0) out_sm[w] = __expf(g_score[w]) / g_sumexp;
        return;
    }

    // ---- sort path ----
    const int g    = blockIdx.x;
    const int base = g * N_;
    const int i0 = tid, i1 = tid + 1024;

    unsigned long long k0, k1;
    {
        unsigned int a = ~ford(g_score[base + i0]);
        unsigned int b = ~ford(g_score[base + i1]);
        k0 = ((unsigned long long)a << 32) | (unsigned int)i0;
        k1 = ((unsigned long long)b << 32) | (unsigned int)i1;
    }

    // k = 2..32 entirely in registers
    #pragma unroll
    for (int k = 2; k <= 32; k <<= 1)
        for (int j = k >> 1; j >= 1; j >>= 1) { reg_ex(k0, i0, j, k); reg_ex(k1, i1, j, k); }

    // k = 64..2048: SMEM passes for j>=32, register passes for j<=16
    for (int k = 64; k <= N_; k <<= 1) {
        keys[i0] = k0; keys[i1] = k1;
        __syncthreads();
        for (int j = k >> 1; j >= 32; j >>= 1) {
            #pragma unroll
            for (int r = 0; r < 2; r++) {
                int i = tid + r * 1024;
                int ixj = i ^ j;
                if (ixj > i) {
                    unsigned long long a = keys[i], c = keys[ixj];
                    bool up = ((i & k) == 0);
                    if ((a > c) == up) { keys[i] = c; keys[ixj] = a; }
                }
            }
            __syncthreads();
        }
        k0 = keys[i0]; k1 = keys[i1];
        #pragma unroll
        for (int j = 16; j >= 1; j >>= 1) { reg_ex(k0, i0, j, k); reg_ex(k1, i1, j, k); }
    }
    keys[i0] = k0; keys[i1] = k1;
    __syncthreads();

    // flags: 1 = unselected
    flags[i0] = 1; flags[i1] = 1;
    __syncthreads();

    // top K_ = first 1024 sorted entries
    {
        int local = (int)(unsigned int)(keys[tid] & 0xFFFFFFFFull);
        flags[local] = 0;
        int gid = base + local;
        g_perm[g * K_ + tid]   = gid;
        out_perm[g * K_ + tid] = (float)gid;
    }
    __syncthreads();

    // warp-shfl scan over contiguous pairs (3 syncs total)
    {
        int e0 = 2 * tid, e1 = 2 * tid + 1;
        int f0 = flags[e0], f1 = flags[e1];
        int v = f0 + f1;
        int sv = v;
        #pragma unroll
        for (int o = 1; o < 32; o <<= 1) {
            int n = __shfl_up_sync(0xFFFFFFFFu, sv, o);
            if ((tid & 31) >= o) sv += n;
        }
        if ((tid & 31) == 31) woff[(tid >> 5) + 1] = sv;
        __syncthreads();
        if (tid == 0) {
            int run = 0;
            woff[0] = 0;
            #pragma unroll
            for (int wgi = 1; wgi <= 32; ++wgi) { run += woff[wgi]; woff[wgi] = run; }
        }
        __syncthreads();
        int pre = woff[tid >> 5] + (sv - v);     // exclusive prefix for e0
        if (f0) {
            int pos = g * (N_ - K_) + pre;
            g_permc[pos]      = base + e0;
            out_perm_com[pos] = (float)(base + e0);
        }
        if (f1) {
            int pos = g * (N_ - K_) + pre + f0;
            g_permc[pos]      = base + e1;
            out_perm_com[pos] = (float)(base + e1);
        }
    }
}

// dist/com = row copies from out_full (already scaled; L2-warm).
// One warp per output row.
__global__ __launch_bounds__(1024) void emitperm_kernel(const float* __restrict__ out_full,
                                                        float* __restrict__ out_dist,
                                                        float* __restrict__ out_com) {
    int gtid = blockIdx.x * blockDim.x + threadIdx.x;
    int r    = gtid >> 5;
    int lane = gtid & 31;
    int p;
    float* o;
    if (r < BK_) {
        p = g_perm[r];
        o = out_dist + (size_t)r * D_;
    } else {
        int rc = r - BK_;
        p = g_permc[rc];
        o = out_com + (size_t)rc * D_;
    }
    float4 f = __ldg(reinterpret_cast<const float4*>(out_full) + (size_t)p * 32 + lane);
    reinterpret_cast<float4*>(o)[lane] = f;
}

// ---------------- launch ----------------------------------------------------

extern "C" void kernel_launch(void* const* d_in, const int* in_sizes, int n_in,
                              void* d_out, int out_size) {
    const float* feature = (const float*)d_in[0];
    const float* W       = (const float*)d_in[1];
    const float* b       = (const float*)d_in[2];
    const int*   src     = (const int*)d_in[3];
    const int*   dst     = (const int*)d_in[4];

    float* out = (float*)d_out;
    float* out_dist     = out;                                  // BK_*D_
    float* out_com      = out + (size_t)BK_ * D_;               // BK_*D_
    float* out_full     = out + (size_t)2 * BK_ * D_;           // BN_*D_
    float* out_perm     = out + (size_t)2 * BK_ * D_ + (size_t)BN_ * D_;
    float* out_perm_com = out_perm + BK_;
    float* out_sm       = out_perm_com + BK_;

    degdot_kernel<<<2 * NCTA_, 256>>>(src, feature, W);
    msg_kernel<<<(BN_ + 255) / 256, 256>>>();
    scatter_kernel<<<NCTA_, 256>>>(src, dst);
    finalize_kernel<<<(BN_ + 255) / 256, 256>>>(b);
    sortemit_kernel<<<B_ + BN_ / 32, 1024>>>(feature, out_perm, out_perm_com,
                                             out_full, out_sm);
    emitperm_kernel<<<(2 * BK_) / 32, 1024>>>(out_full, out_dist, out_com);
}